// round 15
// baseline (speedup 1.0000x reference)
#include <cuda_runtime.h>
#include <cuda_fp16.h>
#include <cstdint>

#define EMBED 2048
#define NHEAD 16
#define HDIM  128
#define BATCH 2
#define SEQ   2048
#define MROWS (BATCH*SEQ)   // 4096

// Scratch (allocation-free contract: __device__ globals)
__device__ __half g_Q[(size_t)BATCH*NHEAD*SEQ*HDIM];   // [B,H,S,D] fp16
__device__ __half g_K[(size_t)BATCH*NHEAD*SEQ*HDIM];
__device__ __half g_V[(size_t)BATCH*NHEAD*SEQ*HDIM];
__device__ __half g_C[(size_t)MROWS*EMBED];            // ctx [B,S,E] fp16
__device__ __half g_xh[(size_t)MROWS*EMBED];           // x as fp16
__device__ __half g_Wh[(size_t)4*EMBED*EMBED];         // Wq,Wk,Wv,Wo as fp16

__device__ __forceinline__ uint32_t smem_u32(const void* p) {
    uint32_t a;
    asm("{ .reg .u64 t; cvta.to.shared.u64 t, %1; cvt.u32.u64 %0, t; }" : "=r"(a) : "l"(p));
    return a;
}

#define CP_ASYNC16(dst, src) \
    asm volatile("cp.async.cg.shared.global [%0], [%1], 16;" :: "r"(dst), "l"(src))
#define CP_COMMIT()  asm volatile("cp.async.commit_group;" ::: "memory")
#define CP_WAIT0()   asm volatile("cp.async.wait_group 0;" ::: "memory")
#define CP_WAIT1()   asm volatile("cp.async.wait_group 1;" ::: "memory")

#define LDMATRIX_X4(r0, r1, r2, r3, addr) \
    asm volatile("ldmatrix.sync.aligned.m8n8.x4.shared.b16 {%0,%1,%2,%3}, [%4];" \
                 : "=r"(r0), "=r"(r1), "=r"(r2), "=r"(r3) : "r"(addr))

__device__ __forceinline__ void mma_f16(float c[4], const uint32_t a[4],
                                        uint32_t b0, uint32_t b1) {
    asm("mma.sync.aligned.m16n8k16.row.col.f32.f16.f16.f32 "
        "{%0,%1,%2,%3}, {%4,%5,%6,%7}, {%8,%9}, {%0,%1,%2,%3};"
        : "+f"(c[0]), "+f"(c[1]), "+f"(c[2]), "+f"(c[3])
        : "r"(a[0]), "r"(a[1]), "r"(a[2]), "r"(a[3]), "r"(b0), "r"(b1));
}

__device__ __forceinline__ uint32_t pack2(float lo, float hi) {
    __half2 h = __floats2half2_rn(lo, hi);
    return *(uint32_t*)&h;
}

// ===================== fused fp32 -> fp16 pre-pass (all 5 arrays) ==========
#define XN4 ((MROWS*EMBED)/4)     // 2,097,152
#define WN4 ((EMBED*EMBED)/4)     // 1,048,576 = 2^20
__global__ void f2h_all_kernel(const float* __restrict__ x,
                               const float* __restrict__ Wq,
                               const float* __restrict__ Wk,
                               const float* __restrict__ Wv,
                               const float* __restrict__ Wo,
                               __half* __restrict__ xh,
                               __half* __restrict__ Wh) {
    int i = blockIdx.x * blockDim.x + threadIdx.x;
    const float* src;
    __half* dst;
    int off;
    if (i < XN4) {
        src = x; dst = xh; off = i;
    } else {
        int j = i - XN4;
        int sel = j >> 20;          // WN4 = 2^20
        off = j & (WN4 - 1);
        const float* ws[4] = {Wq, Wk, Wv, Wo};
        src = ws[sel];
        dst = Wh + (size_t)sel * (EMBED * (size_t)EMBED);
    }
    float4 v = ((const float4*)src)[off];
    __half2 a = __floats2half2_rn(v.x, v.y);
    __half2 b = __floats2half2_rn(v.z, v.w);
    uint2 u;
    u.x = *(uint32_t*)&a;
    u.y = *(uint32_t*)&b;
    ((uint2*)dst)[off] = u;
}

// ---------------------------------------------------------------------------
// FP16 GEMM v7: 128x128 tile, K-tile 64 (32 iterations, HALF the barriers),
// 8 warps, warp tile 64x32, ldmatrix fragments (R10-proven lane maps).
// Smem rows: 128-B payload + 16-B pad = 144 B (9r mod 8 full-period ->
// cp.async + ldmatrix conflict-free).  3-stage ring, 2 tiles in flight.
// Global K order identical to R10/R13 -> bit-identical accumulation.
// mode 0: fp32 out row-major [M,N] (W=Wbase, bias=b0, out=o0).
// mode 1: QKV fused; blockIdx.z in {0,1,2} selects W slab / bias / output,
//         half out scattered to [B,H,S,D].
// ---------------------------------------------------------------------------
#define GPS 144                       // smem row stride, bytes
#define STAGE_B (256*GPS)             // A(128 rows)+B(128 rows) = 36,864 B
#define NSTAGE 3
#define GEMM_SMEM (NSTAGE*STAGE_B)    // 110,592 B

__global__ void __launch_bounds__(256) gemm_f16_kernel(
    const __half* __restrict__ A, const __half* __restrict__ Wbase,
    const float* __restrict__ b0, const float* __restrict__ b1,
    const float* __restrict__ b2,
    void* __restrict__ o0, void* __restrict__ o1, void* __restrict__ o2,
    int mode)
{
    extern __shared__ char gsm[];
    const int K = EMBED;

    int z = blockIdx.z;
    const __half* W = Wbase + (size_t)z * EMBED * EMBED;
    const float* bias = (z == 0) ? b0 : ((z == 1) ? b1 : b2);
    void* Cv = (z == 0) ? o0 : ((z == 1) ? o1 : o2);

    int tid  = threadIdx.x;
    int lane = tid & 31, wid = tid >> 5;
    int tig  = lane & 3, grp = lane >> 2;
    int wm   = (wid >> 2) * 64;
    int wn   = (wid & 3) * 32;
    int bm   = blockIdx.y * 128, bn = blockIdx.x * 128;

    // cp.async geometry: K-tile row = 128 B = 8 chunks; thread t -> row t>>1,
    // 4 chunks at byte (t&1)*64.
    int r   = tid >> 1;
    int cb  = (tid & 1) * 64;
    const char* gA = (const char*)(A + (size_t)(bm + r) * K) + cb;
    const char* gB = (const char*)(W + (size_t)(bn + r) * K) + cb;
    uint32_t sb = smem_u32(gsm);
    uint32_t dA = sb + r * GPS + cb;
    uint32_t dB = dA + 128 * GPS;

    uint32_t aFragB = sb + (uint32_t)(wm + (lane & 7) + ((lane >> 3) & 1) * 8) * GPS
                    + (uint32_t)(lane >> 4) * 16;
    uint32_t bFragB = sb + 128 * GPS
                    + (uint32_t)(wn + (lane & 7) + ((lane >> 4) & 1) * 8) * GPS
                    + (uint32_t)((lane >> 3) & 1) * 16;

    float acc[4][4][4];
#pragma unroll
    for (int i = 0; i < 4; i++)
#pragma unroll
        for (int j = 0; j < 4; j++)
#pragma unroll
            for (int q = 0; q < 4; q++) acc[i][j][q] = 0.f;

    // prologue: K-tiles 0,1 -> stages 0,1
#pragma unroll
    for (int t = 0; t < 2; t++) {
        uint32_t so = t * STAGE_B;
        const char* a = gA + (size_t)t * 128;
        const char* b = gB + (size_t)t * 128;
#pragma unroll
        for (int c = 0; c < 4; c++) CP_ASYNC16(dA + so + c * 16, a + c * 16);
#pragma unroll
        for (int c = 0; c < 4; c++) CP_ASYNC16(dB + so + c * 16, b + c * 16);
        CP_COMMIT();
    }

    for (int kt = 0; kt < 32; kt++) {
        if (kt < 31) CP_WAIT1(); else CP_WAIT0();
        __syncthreads();
        if (kt + 2 < 32) {                         // refill stage (kt+2)%3
            int t = kt + 2;
            uint32_t so = (t % NSTAGE) * STAGE_B;
            const char* a = gA + (size_t)t * 128;
            const char* b = gB + (size_t)t * 128;
#pragma unroll
            for (int c = 0; c < 4; c++) CP_ASYNC16(dA + so + c * 16, a + c * 16);
#pragma unroll
            for (int c = 0; c < 4; c++) CP_ASYNC16(dB + so + c * 16, b + c * 16);
            CP_COMMIT();
        }

        uint32_t so = (kt % NSTAGE) * STAGE_B;
#pragma unroll
        for (int ks = 0; ks < 4; ks++) {           // 4 x k16 per 64-K tile
            uint32_t kso = so + ks * 32;
            uint32_t a[4][4], b[4][2];
#pragma unroll
            for (int mi = 0; mi < 4; mi++)
                LDMATRIX_X4(a[mi][0], a[mi][1], a[mi][2], a[mi][3],
                            aFragB + kso + (uint32_t)(mi * 16 * GPS));
#pragma unroll
            for (int pr = 0; pr < 2; pr++)
                LDMATRIX_X4(b[2*pr][0], b[2*pr][1], b[2*pr+1][0], b[2*pr+1][1],
                            bFragB + kso + (uint32_t)(pr * 16 * GPS));
#pragma unroll
            for (int mi = 0; mi < 4; mi++)
#pragma unroll
                for (int ni = 0; ni < 4; ni++)
                    mma_f16(acc[mi][ni], a[mi], b[ni][0], b[ni][1]);
        }
    }

#pragma unroll
    for (int mi = 0; mi < 4; mi++) {
#pragma unroll
        for (int ni = 0; ni < 4; ni++) {
            int m0 = bm + wm + mi * 16 + grp;
            int n0 = bn + wn + ni * 8 + tig * 2;
            float bv0 = bias[n0], bv1 = bias[n0 + 1];
            float v00 = acc[mi][ni][0] + bv0, v01 = acc[mi][ni][1] + bv1;
            float v10 = acc[mi][ni][2] + bv0, v11 = acc[mi][ni][3] + bv1;
            if (mode == 0) {
                float* C = (float*)Cv;
                C[(size_t)m0 * EMBED + n0]       = v00;
                C[(size_t)m0 * EMBED + n0 + 1]   = v01;
                C[(size_t)(m0+8) * EMBED + n0]   = v10;
                C[(size_t)(m0+8) * EMBED + n0+1] = v11;
            } else {
                __half* C = (__half*)Cv;
                size_t i0 = ((size_t)((m0 >> 11) * NHEAD + (n0 >> 7))) * (SEQ * HDIM)
                          + (size_t)(m0 & (SEQ-1)) * HDIM + (n0 & (HDIM-1));
                size_t i1 = ((size_t)(((m0+8) >> 11) * NHEAD + (n0 >> 7))) * (SEQ * HDIM)
                          + (size_t)((m0+8) & (SEQ-1)) * HDIM + (n0 & (HDIM-1));
                *(__half2*)(C + i0) = __floats2half2_rn(v00, v01);
                *(__half2*)(C + i1) = __floats2half2_rn(v10, v11);
            }
        }
    }
}

// ---------------------------------------------------------------------------
// Causal flash attention v5 — R10-proven, unchanged.
// ---------------------------------------------------------------------------
#define AS 136
#define ATTN_SMEM (3*64*AS*2)   // 52,224 B

__global__ void __launch_bounds__(128, 2) attn_kernel(
    const __half* __restrict__ Q, const __half* __restrict__ K,
    const __half* __restrict__ V, __half* __restrict__ Ctx)
{
    extern __shared__ __half hsm[];
    __half* Qs = hsm;              // [64][AS]
    __half* Ks = hsm + 64*AS;      // [64][AS]
    __half* Vs = hsm + 2*64*AS;    // [64][AS]

    int tid  = threadIdx.x;
    int lane = tid & 31, wid = tid >> 5;          // 4 warps
    int tig  = lane & 3, grp = lane >> 2;
    int bh   = blockIdx.y;
    int qt   = gridDim.x - 1 - blockIdx.x;        // big-work blocks first
    int q0   = qt * 64;
    int wrow = wid * 16;

    const size_t off = (size_t)bh * SEQ * HDIM;
    const __half* Qp = Q + off + (size_t)q0 * HDIM;
    const __half* Kp = K + off;
    const __half* Vp = V + off;
    const float scale = 0.08838834764831845f;     // 1/sqrt(128)

#pragma unroll
    for (int p = 0; p < 8; p++) {
        int f = tid + p * 128;
        int r = f >> 4, c = (f & 15) * 8;
        *(uint4*)(Qs + r * AS + c) = *(const uint4*)(Qp + (size_t)r * HDIM + c);
    }
    __syncthreads();

    uint32_t qf[8][4];
#pragma unroll
    for (int ks = 0; ks < 8; ks++) {
        int kb = ks * 16 + 2 * tig;
        qf[ks][0] = *(const uint32_t*)(Qs + (wrow + grp    ) * AS + kb    );
        qf[ks][1] = *(const uint32_t*)(Qs + (wrow + grp + 8) * AS + kb    );
        qf[ks][2] = *(const uint32_t*)(Qs + (wrow + grp    ) * AS + kb + 8);
        qf[ks][3] = *(const uint32_t*)(Qs + (wrow + grp + 8) * AS + kb + 8);
    }

    float o[16][4];
#pragma unroll
    for (int i = 0; i < 16; i++)
#pragma unroll
        for (int r2 = 0; r2 < 4; r2++) o[i][r2] = 0.f;
    float m_lo = -1e30f, m_hi = -1e30f, l_lo = 0.f, l_hi = 0.f;

    int row_lo = q0 + wrow + grp;
    int row_hi = row_lo + 8;

    uint32_t kFragB = smem_u32(Ks)
                    + (uint32_t)((lane & 7) + ((lane >> 4) & 1) * 8) * (AS*2)
                    + (uint32_t)((lane >> 3) & 1) * 16;

    int lro = (lane & 7) + ((lane >> 3) & 1) * 8;
    int lco = (lane >> 4) * 8;
    uint32_t vbase = smem_u32(Vs);

    for (int kt = 0; kt <= qt; kt++) {
        __syncthreads();
#pragma unroll
        for (int p = 0; p < 8; p++) {
            int f = tid + p * 128;
            int r = f >> 4, c = (f & 15) * 8;
            *(uint4*)(Ks + r * AS + c) =
                *(const uint4*)(Kp + (size_t)(kt * 64 + r) * HDIM + c);
            *(uint4*)(Vs + r * AS + c) =
                *(const uint4*)(Vp + (size_t)(kt * 64 + r) * HDIM + c);
        }
        __syncthreads();

        float s[8][4];
#pragma unroll
        for (int i = 0; i < 8; i++)
#pragma unroll
            for (int r2 = 0; r2 < 4; r2++) s[i][r2] = 0.f;
#pragma unroll
        for (int ks = 0; ks < 8; ks++) {
            uint32_t kso = (uint32_t)(ks * 32);
#pragma unroll
            for (int pr = 0; pr < 4; pr++) {
                uint32_t b00, b01, b10, b11;
                LDMATRIX_X4(b00, b01, b10, b11,
                            kFragB + kso + (uint32_t)(pr * 16 * (AS*2)));
                mma_f16(s[2*pr    ], qf[ks], b00, b01);
                mma_f16(s[2*pr + 1], qf[ks], b10, b11);
            }
        }
#pragma unroll
        for (int ni = 0; ni < 8; ni++) {
            s[ni][0] *= scale; s[ni][1] *= scale;
            s[ni][2] *= scale; s[ni][3] *= scale;
        }

        if (kt == qt) {
            int colbase = kt * 64 + tig * 2;
#pragma unroll
            for (int ni = 0; ni < 8; ni++) {
                int c0 = colbase + ni * 8, c1 = c0 + 1;
                if (c0 > row_lo) s[ni][0] = -1e9f;
                if (c1 > row_lo) s[ni][1] = -1e9f;
                if (c0 > row_hi) s[ni][2] = -1e9f;
                if (c1 > row_hi) s[ni][3] = -1e9f;
            }
        }

        float tmax_lo = -1e30f, tmax_hi = -1e30f;
#pragma unroll
        for (int ni = 0; ni < 8; ni++) {
            tmax_lo = fmaxf(tmax_lo, fmaxf(s[ni][0], s[ni][1]));
            tmax_hi = fmaxf(tmax_hi, fmaxf(s[ni][2], s[ni][3]));
        }
#pragma unroll
        for (int o2 = 1; o2 < 4; o2 <<= 1) {
            tmax_lo = fmaxf(tmax_lo, __shfl_xor_sync(0xffffffffu, tmax_lo, o2));
            tmax_hi = fmaxf(tmax_hi, __shfl_xor_sync(0xffffffffu, tmax_hi, o2));
        }
        float mn_lo = fmaxf(m_lo, tmax_lo), mn_hi = fmaxf(m_hi, tmax_hi);
        float al = __expf(m_lo - mn_lo), ah = __expf(m_hi - mn_hi);
        m_lo = mn_lo; m_hi = mn_hi;

        float sum_lo = 0.f, sum_hi = 0.f;
#pragma unroll
        for (int ni = 0; ni < 8; ni++) {
            s[ni][0] = __expf(s[ni][0] - m_lo);
            s[ni][1] = __expf(s[ni][1] - m_lo);
            s[ni][2] = __expf(s[ni][2] - m_hi);
            s[ni][3] = __expf(s[ni][3] - m_hi);
            sum_lo += s[ni][0] + s[ni][1];
            sum_hi += s[ni][2] + s[ni][3];
        }
#pragma unroll
        for (int o2 = 1; o2 < 4; o2 <<= 1) {
            sum_lo += __shfl_xor_sync(0xffffffffu, sum_lo, o2);
            sum_hi += __shfl_xor_sync(0xffffffffu, sum_hi, o2);
        }
        l_lo = l_lo * al + sum_lo;
        l_hi = l_hi * ah + sum_hi;
#pragma unroll
        for (int ni = 0; ni < 16; ni++) {
            o[ni][0] *= al; o[ni][1] *= al;
            o[ni][2] *= ah; o[ni][3] *= ah;
        }

#pragma unroll
        for (int ks2 = 0; ks2 < 4; ks2++) {
            uint32_t a[4];
            a[0] = pack2(s[2*ks2  ][0], s[2*ks2  ][1]);
            a[1] = pack2(s[2*ks2  ][2], s[2*ks2  ][3]);
            a[2] = pack2(s[2*ks2+1][0], s[2*ks2+1][1]);
            a[3] = pack2(s[2*ks2+1][2], s[2*ks2+1][3]);
            uint32_t rowaddr = vbase + (uint32_t)(((ks2*16 + lro) * AS + lco) * 2);
#pragma unroll
            for (int ni2 = 0; ni2 < 8; ni2++) {
                uint32_t b00, b01, b10, b11;
                asm volatile(
                    "ldmatrix.sync.aligned.m8n8.x4.trans.shared.b16 "
                    "{%0,%1,%2,%3}, [%4];"
                    : "=r"(b00), "=r"(b01), "=r"(b10), "=r"(b11)
                    : "r"(rowaddr + (uint32_t)(ni2 * 16 * 2)));
                mma_f16(o[2*ni2    ], a, b00, b01);
                mma_f16(o[2*ni2 + 1], a, b10, b11);
            }
        }
    }

    int b = bh >> 4, h = bh & 15;
    size_t base_lo = ((size_t)b * SEQ + row_lo) * EMBED + h * HDIM;
    size_t base_hi = base_lo + (size_t)8 * EMBED;
    float il_lo = 1.f / l_lo, il_hi = 1.f / l_hi;
#pragma unroll
    for (int ni = 0; ni < 16; ni++) {
        int c = ni * 8 + tig * 2;
        *(__half2*)(Ctx + base_lo + c) = __floats2half2_rn(o[ni][0]*il_lo, o[ni][1]*il_lo);
        *(__half2*)(Ctx + base_hi + c) = __floats2half2_rn(o[ni][2]*il_hi, o[ni][3]*il_hi);
    }
}

// ---------------------------------------------------------------------------
extern "C" void kernel_launch(void* const* d_in, const int* in_sizes, int n_in,
                              void* d_out, int out_size) {
    const float* x  = (const float*)d_in[0];
    const float* Wq = (const float*)d_in[1];
    const float* bq = (const float*)d_in[2];
    const float* Wk = (const float*)d_in[3];
    const float* bk = (const float*)d_in[4];
    const float* Wv = (const float*)d_in[5];
    const float* bv = (const float*)d_in[6];
    const float* Wo = (const float*)d_in[7];
    const float* bo = (const float*)d_in[8];
    float* out = (float*)d_out;

    __half *Qb, *Kb, *Vb, *Cb, *xh, *Wh;
    cudaGetSymbolAddress((void**)&Qb, g_Q);
    cudaGetSymbolAddress((void**)&Kb, g_K);
    cudaGetSymbolAddress((void**)&Vb, g_V);
    cudaGetSymbolAddress((void**)&Cb, g_C);
    cudaGetSymbolAddress((void**)&xh, g_xh);
    cudaGetSymbolAddress((void**)&Wh, g_Wh);
    __half* Woh = Wh + (size_t)3 * EMBED * EMBED;

    const int total4 = XN4 + 4 * WN4;   // 6,291,456
    f2h_all_kernel<<<total4 / 256, 256>>>(x, Wq, Wk, Wv, Wo, xh, Wh);

    cudaFuncSetAttribute(gemm_f16_kernel,
                         cudaFuncAttributeMaxDynamicSharedMemorySize, GEMM_SMEM);

    // Fused QKV: grid.z = 3 selects Wq/Wk/Wv slab of Wh, bias, output.
    dim3 gqkv(EMBED / 128, MROWS / 128, 3);   // 1536 CTAs
    gemm_f16_kernel<<<gqkv, 256, GEMM_SMEM>>>(xh, Wh, bq, bk, bv,
                                              Qb, Kb, Vb, 1);

    cudaFuncSetAttribute(attn_kernel,
                         cudaFuncAttributeMaxDynamicSharedMemorySize, ATTN_SMEM);
    attn_kernel<<<dim3(SEQ / 64, BATCH * NHEAD), 128, ATTN_SMEM>>>(Qb, Kb, Vb, Cb);

    // O-projection: single slab (z=0 -> Woh, bo, out), fp32 out.
    dim3 go(EMBED / 128, MROWS / 128, 1);     // 512 CTAs
    gemm_f16_kernel<<<go, 256, GEMM_SMEM>>>(Cb, Woh, bo, bo, bo,
                                            out, out, out, 0);
}

// round 16
// speedup vs baseline: 1.0826x; 1.0826x over previous
#include <cuda_runtime.h>
#include <cuda_fp16.h>
#include <cstdint>

#define EMBED 2048
#define NHEAD 16
#define HDIM  128
#define BATCH 2
#define SEQ   2048
#define MROWS (BATCH*SEQ)   // 4096

// Scratch (allocation-free contract: __device__ globals)
__device__ __half g_Q[(size_t)BATCH*NHEAD*SEQ*HDIM];   // [B,H,S,D] fp16
__device__ __half g_K[(size_t)BATCH*NHEAD*SEQ*HDIM];
__device__ __half g_V[(size_t)BATCH*NHEAD*SEQ*HDIM];
__device__ __half g_C[(size_t)MROWS*EMBED];            // ctx [B,S,E] fp16
__device__ __half g_xh[(size_t)MROWS*EMBED];           // x as fp16
__device__ __half g_Wh[(size_t)4*EMBED*EMBED];         // Wq,Wk,Wv,Wo as fp16

__device__ __forceinline__ uint32_t smem_u32(const void* p) {
    uint32_t a;
    asm("{ .reg .u64 t; cvta.to.shared.u64 t, %1; cvt.u32.u64 %0, t; }" : "=r"(a) : "l"(p));
    return a;
}

#define CP_ASYNC16(dst, src) \
    asm volatile("cp.async.cg.shared.global [%0], [%1], 16;" :: "r"(dst), "l"(src))
#define CP_COMMIT()  asm volatile("cp.async.commit_group;" ::: "memory")
#define CP_WAIT0()   asm volatile("cp.async.wait_group 0;" ::: "memory")
#define CP_WAIT1()   asm volatile("cp.async.wait_group 1;" ::: "memory")

#define LDMATRIX_X4(r0, r1, r2, r3, addr) \
    asm volatile("ldmatrix.sync.aligned.m8n8.x4.shared.b16 {%0,%1,%2,%3}, [%4];" \
                 : "=r"(r0), "=r"(r1), "=r"(r2), "=r"(r3) : "r"(addr))

__device__ __forceinline__ void mma_f16(float c[4], const uint32_t a[4],
                                        uint32_t b0, uint32_t b1) {
    asm("mma.sync.aligned.m16n8k16.row.col.f32.f16.f16.f32 "
        "{%0,%1,%2,%3}, {%4,%5,%6,%7}, {%8,%9}, {%0,%1,%2,%3};"
        : "+f"(c[0]), "+f"(c[1]), "+f"(c[2]), "+f"(c[3])
        : "r"(a[0]), "r"(a[1]), "r"(a[2]), "r"(a[3]), "r"(b0), "r"(b1));
}

__device__ __forceinline__ uint32_t pack2(float lo, float hi) {
    __half2 h = __floats2half2_rn(lo, hi);
    return *(uint32_t*)&h;
}

// ===================== fused fp32 -> fp16 pre-pass (all 5 arrays) ==========
#define XN4 ((MROWS*EMBED)/4)     // 2,097,152
#define WN4 ((EMBED*EMBED)/4)     // 1,048,576 = 2^20
__global__ void f2h_all_kernel(const float* __restrict__ x,
                               const float* __restrict__ Wq,
                               const float* __restrict__ Wk,
                               const float* __restrict__ Wv,
                               const float* __restrict__ Wo,
                               __half* __restrict__ xh,
                               __half* __restrict__ Wh) {
    int i = blockIdx.x * blockDim.x + threadIdx.x;
    const float* src;
    __half* dst;
    int off;
    if (i < XN4) {
        src = x; dst = xh; off = i;
    } else {
        int j = i - XN4;
        int sel = j >> 20;          // WN4 = 2^20
        off = j & (WN4 - 1);
        const float* ws[4] = {Wq, Wk, Wv, Wo};
        src = ws[sel];
        dst = Wh + (size_t)sel * (EMBED * (size_t)EMBED);
    }
    float4 v = ((const float4*)src)[off];
    __half2 a = __floats2half2_rn(v.x, v.y);
    __half2 b = __floats2half2_rn(v.z, v.w);
    uint2 u;
    u.x = *(uint32_t*)&a;
    u.y = *(uint32_t*)&b;
    ((uint2*)dst)[off] = u;
}

// ---------------------------------------------------------------------------
// FP16 GEMM (R12-proven body, 147.9us/eq-launch): 128x128 tile, K-tile 32,
// 8 warps, warp tile 64x32, 3-stage cp.async ring, 1 barrier/tile, ldmatrix.
// GPS=112 B rows: 7r mod 8 distinct -> cp.async + ldmatrix conflict-free.
// z-dispatch: blockIdx.z selects W slab, bias, output (QKV fused in 1 launch).
// mode 0: fp32 out row-major [M,N].  mode 1: HALF out scatter to [B,H,S,D].
// ---------------------------------------------------------------------------
#define GPS 112                       // smem row stride, bytes
#define STAGE_B (128*GPS*2)           // A+B per stage = 28,672 B
#define NSTAGE 3
#define GEMM_SMEM (NSTAGE*STAGE_B)    // 86,016 B

__global__ void __launch_bounds__(256) gemm_f16_kernel(
    const __half* __restrict__ A, const __half* __restrict__ Wbase,
    const float* __restrict__ b0, const float* __restrict__ b1,
    const float* __restrict__ b2,
    void* __restrict__ o0, void* __restrict__ o1, void* __restrict__ o2,
    int mode)
{
    extern __shared__ char gsm[];
    const int K = EMBED;

    int z = blockIdx.z;
    const __half* W = Wbase + (size_t)z * EMBED * EMBED;
    const float* bias = (z == 0) ? b0 : ((z == 1) ? b1 : b2);
    void* Cv = (z == 0) ? o0 : ((z == 1) ? o1 : o2);

    int tid  = threadIdx.x;
    int lane = tid & 31, wid = tid >> 5;
    int tig  = lane & 3, grp = lane >> 2;
    int wm   = (wid >> 2) * 64;
    int wn   = (wid & 3) * 32;
    int bm   = blockIdx.y * 128, bn = blockIdx.x * 128;

    int r   = tid >> 1;
    int ch0 = (tid & 1) * 2;
    const char* gA = (const char*)(A + (size_t)(bm + r) * K) + ch0 * 16;
    const char* gB = (const char*)(W + (size_t)(bn + r) * K) + ch0 * 16;
    uint32_t sb = smem_u32(gsm);
    uint32_t dA = sb + r * GPS + ch0 * 16;
    uint32_t dB = dA + 128 * GPS;

    uint32_t aFragB = sb + (uint32_t)(wm + (lane & 7) + ((lane >> 3) & 1) * 8) * GPS
                    + (uint32_t)(lane >> 4) * 16;
    uint32_t bFragB = sb + 128 * GPS
                    + (uint32_t)(wn + (lane & 7) + ((lane >> 4) & 1) * 8) * GPS
                    + (uint32_t)((lane >> 3) & 1) * 16;

    float acc[4][4][4];
#pragma unroll
    for (int i = 0; i < 4; i++)
#pragma unroll
        for (int j = 0; j < 4; j++)
#pragma unroll
            for (int q = 0; q < 4; q++) acc[i][j][q] = 0.f;

#pragma unroll
    for (int t = 0; t < 2; t++) {
        uint32_t so = t * STAGE_B;
        const char* a = gA + (size_t)t * 64;
        const char* b = gB + (size_t)t * 64;
        CP_ASYNC16(dA + so, a);  CP_ASYNC16(dA + so + 16, a + 16);
        CP_ASYNC16(dB + so, b);  CP_ASYNC16(dB + so + 16, b + 16);
        CP_COMMIT();
    }

    for (int kt = 0; kt < 64; kt++) {
        if (kt < 63) CP_WAIT1(); else CP_WAIT0();
        __syncthreads();
        if (kt + 2 < 64) {
            int t = kt + 2;
            uint32_t so = (t % NSTAGE) * STAGE_B;
            const char* a = gA + (size_t)t * 64;
            const char* b = gB + (size_t)t * 64;
            CP_ASYNC16(dA + so, a);  CP_ASYNC16(dA + so + 16, a + 16);
            CP_ASYNC16(dB + so, b);  CP_ASYNC16(dB + so + 16, b + 16);
            CP_COMMIT();
        }

        uint32_t so = (kt % NSTAGE) * STAGE_B;
#pragma unroll
        for (int ks = 0; ks < 2; ks++) {
            uint32_t kso = so + ks * 32;           // k16 chunk = 32 B
            uint32_t a[4][4], b[4][2];
#pragma unroll
            for (int mi = 0; mi < 4; mi++)
                LDMATRIX_X4(a[mi][0], a[mi][1], a[mi][2], a[mi][3],
                            aFragB + kso + (uint32_t)(mi * 16 * GPS));
#pragma unroll
            for (int pr = 0; pr < 2; pr++)
                LDMATRIX_X4(b[2*pr][0], b[2*pr][1], b[2*pr+1][0], b[2*pr+1][1],
                            bFragB + kso + (uint32_t)(pr * 16 * GPS));
#pragma unroll
            for (int mi = 0; mi < 4; mi++)
#pragma unroll
                for (int ni = 0; ni < 4; ni++)
                    mma_f16(acc[mi][ni], a[mi], b[ni][0], b[ni][1]);
        }
    }

#pragma unroll
    for (int mi = 0; mi < 4; mi++) {
#pragma unroll
        for (int ni = 0; ni < 4; ni++) {
            int m0 = bm + wm + mi * 16 + grp;
            int n0 = bn + wn + ni * 8 + tig * 2;
            float bv0 = bias[n0], bv1 = bias[n0 + 1];
            float v00 = acc[mi][ni][0] + bv0, v01 = acc[mi][ni][1] + bv1;
            float v10 = acc[mi][ni][2] + bv0, v11 = acc[mi][ni][3] + bv1;
            if (mode == 0) {
                float* C = (float*)Cv;
                C[(size_t)m0 * EMBED + n0]       = v00;
                C[(size_t)m0 * EMBED + n0 + 1]   = v01;
                C[(size_t)(m0+8) * EMBED + n0]   = v10;
                C[(size_t)(m0+8) * EMBED + n0+1] = v11;
            } else {
                __half* C = (__half*)Cv;
                size_t i0 = ((size_t)((m0 >> 11) * NHEAD + (n0 >> 7))) * (SEQ * HDIM)
                          + (size_t)(m0 & (SEQ-1)) * HDIM + (n0 & (HDIM-1));
                size_t i1 = ((size_t)(((m0+8) >> 11) * NHEAD + (n0 >> 7))) * (SEQ * HDIM)
                          + (size_t)((m0+8) & (SEQ-1)) * HDIM + (n0 & (HDIM-1));
                *(__half2*)(C + i0) = __floats2half2_rn(v00, v01);
                *(__half2*)(C + i1) = __floats2half2_rn(v10, v11);
            }
        }
    }
}

// ---------------------------------------------------------------------------
// Causal flash attention v5 — R10-proven, unchanged.
// ---------------------------------------------------------------------------
#define AS 136
#define ATTN_SMEM (3*64*AS*2)   // 52,224 B

__global__ void __launch_bounds__(128, 2) attn_kernel(
    const __half* __restrict__ Q, const __half* __restrict__ K,
    const __half* __restrict__ V, __half* __restrict__ Ctx)
{
    extern __shared__ __half hsm[];
    __half* Qs = hsm;              // [64][AS]
    __half* Ks = hsm + 64*AS;      // [64][AS]
    __half* Vs = hsm + 2*64*AS;    // [64][AS]

    int tid  = threadIdx.x;
    int lane = tid & 31, wid = tid >> 5;          // 4 warps
    int tig  = lane & 3, grp = lane >> 2;
    int bh   = blockIdx.y;
    int qt   = gridDim.x - 1 - blockIdx.x;        // big-work blocks first
    int q0   = qt * 64;
    int wrow = wid * 16;

    const size_t off = (size_t)bh * SEQ * HDIM;
    const __half* Qp = Q + off + (size_t)q0 * HDIM;
    const __half* Kp = K + off;
    const __half* Vp = V + off;
    const float scale = 0.08838834764831845f;     // 1/sqrt(128)

#pragma unroll
    for (int p = 0; p < 8; p++) {
        int f = tid + p * 128;
        int r = f >> 4, c = (f & 15) * 8;
        *(uint4*)(Qs + r * AS + c) = *(const uint4*)(Qp + (size_t)r * HDIM + c);
    }
    __syncthreads();

    uint32_t qf[8][4];
#pragma unroll
    for (int ks = 0; ks < 8; ks++) {
        int kb = ks * 16 + 2 * tig;
        qf[ks][0] = *(const uint32_t*)(Qs + (wrow + grp    ) * AS + kb    );
        qf[ks][1] = *(const uint32_t*)(Qs + (wrow + grp + 8) * AS + kb    );
        qf[ks][2] = *(const uint32_t*)(Qs + (wrow + grp    ) * AS + kb + 8);
        qf[ks][3] = *(const uint32_t*)(Qs + (wrow + grp + 8) * AS + kb + 8);
    }

    float o[16][4];
#pragma unroll
    for (int i = 0; i < 16; i++)
#pragma unroll
        for (int r2 = 0; r2 < 4; r2++) o[i][r2] = 0.f;
    float m_lo = -1e30f, m_hi = -1e30f, l_lo = 0.f, l_hi = 0.f;

    int row_lo = q0 + wrow + grp;
    int row_hi = row_lo + 8;

    uint32_t kFragB = smem_u32(Ks)
                    + (uint32_t)((lane & 7) + ((lane >> 4) & 1) * 8) * (AS*2)
                    + (uint32_t)((lane >> 3) & 1) * 16;

    int lro = (lane & 7) + ((lane >> 3) & 1) * 8;
    int lco = (lane >> 4) * 8;
    uint32_t vbase = smem_u32(Vs);

    for (int kt = 0; kt <= qt; kt++) {
        __syncthreads();
#pragma unroll
        for (int p = 0; p < 8; p++) {
            int f = tid + p * 128;
            int r = f >> 4, c = (f & 15) * 8;
            *(uint4*)(Ks + r * AS + c) =
                *(const uint4*)(Kp + (size_t)(kt * 64 + r) * HDIM + c);
            *(uint4*)(Vs + r * AS + c) =
                *(const uint4*)(Vp + (size_t)(kt * 64 + r) * HDIM + c);
        }
        __syncthreads();

        float s[8][4];
#pragma unroll
        for (int i = 0; i < 8; i++)
#pragma unroll
            for (int r2 = 0; r2 < 4; r2++) s[i][r2] = 0.f;
#pragma unroll
        for (int ks = 0; ks < 8; ks++) {
            uint32_t kso = (uint32_t)(ks * 32);
#pragma unroll
            for (int pr = 0; pr < 4; pr++) {
                uint32_t b00, b01, b10, b11;
                LDMATRIX_X4(b00, b01, b10, b11,
                            kFragB + kso + (uint32_t)(pr * 16 * (AS*2)));
                mma_f16(s[2*pr    ], qf[ks], b00, b01);
                mma_f16(s[2*pr + 1], qf[ks], b10, b11);
            }
        }
#pragma unroll
        for (int ni = 0; ni < 8; ni++) {
            s[ni][0] *= scale; s[ni][1] *= scale;
            s[ni][2] *= scale; s[ni][3] *= scale;
        }

        if (kt == qt) {
            int colbase = kt * 64 + tig * 2;
#pragma unroll
            for (int ni = 0; ni < 8; ni++) {
                int c0 = colbase + ni * 8, c1 = c0 + 1;
                if (c0 > row_lo) s[ni][0] = -1e9f;
                if (c1 > row_lo) s[ni][1] = -1e9f;
                if (c0 > row_hi) s[ni][2] = -1e9f;
                if (c1 > row_hi) s[ni][3] = -1e9f;
            }
        }

        float tmax_lo = -1e30f, tmax_hi = -1e30f;
#pragma unroll
        for (int ni = 0; ni < 8; ni++) {
            tmax_lo = fmaxf(tmax_lo, fmaxf(s[ni][0], s[ni][1]));
            tmax_hi = fmaxf(tmax_hi, fmaxf(s[ni][2], s[ni][3]));
        }
#pragma unroll
        for (int o2 = 1; o2 < 4; o2 <<= 1) {
            tmax_lo = fmaxf(tmax_lo, __shfl_xor_sync(0xffffffffu, tmax_lo, o2));
            tmax_hi = fmaxf(tmax_hi, __shfl_xor_sync(0xffffffffu, tmax_hi, o2));
        }
        float mn_lo = fmaxf(m_lo, tmax_lo), mn_hi = fmaxf(m_hi, tmax_hi);
        float al = __expf(m_lo - mn_lo), ah = __expf(m_hi - mn_hi);
        m_lo = mn_lo; m_hi = mn_hi;

        float sum_lo = 0.f, sum_hi = 0.f;
#pragma unroll
        for (int ni = 0; ni < 8; ni++) {
            s[ni][0] = __expf(s[ni][0] - m_lo);
            s[ni][1] = __expf(s[ni][1] - m_lo);
            s[ni][2] = __expf(s[ni][2] - m_hi);
            s[ni][3] = __expf(s[ni][3] - m_hi);
            sum_lo += s[ni][0] + s[ni][1];
            sum_hi += s[ni][2] + s[ni][3];
        }
#pragma unroll
        for (int o2 = 1; o2 < 4; o2 <<= 1) {
            sum_lo += __shfl_xor_sync(0xffffffffu, sum_lo, o2);
            sum_hi += __shfl_xor_sync(0xffffffffu, sum_hi, o2);
        }
        l_lo = l_lo * al + sum_lo;
        l_hi = l_hi * ah + sum_hi;
#pragma unroll
        for (int ni = 0; ni < 16; ni++) {
            o[ni][0] *= al; o[ni][1] *= al;
            o[ni][2] *= ah; o[ni][3] *= ah;
        }

#pragma unroll
        for (int ks2 = 0; ks2 < 4; ks2++) {
            uint32_t a[4];
            a[0] = pack2(s[2*ks2  ][0], s[2*ks2  ][1]);
            a[1] = pack2(s[2*ks2  ][2], s[2*ks2  ][3]);
            a[2] = pack2(s[2*ks2+1][0], s[2*ks2+1][1]);
            a[3] = pack2(s[2*ks2+1][2], s[2*ks2+1][3]);
            uint32_t rowaddr = vbase + (uint32_t)(((ks2*16 + lro) * AS + lco) * 2);
#pragma unroll
            for (int ni2 = 0; ni2 < 8; ni2++) {
                uint32_t b00, b01, b10, b11;
                asm volatile(
                    "ldmatrix.sync.aligned.m8n8.x4.trans.shared.b16 "
                    "{%0,%1,%2,%3}, [%4];"
                    : "=r"(b00), "=r"(b01), "=r"(b10), "=r"(b11)
                    : "r"(rowaddr + (uint32_t)(ni2 * 16 * 2)));
                mma_f16(o[2*ni2    ], a, b00, b01);
                mma_f16(o[2*ni2 + 1], a, b10, b11);
            }
        }
    }

    int b = bh >> 4, h = bh & 15;
    size_t base_lo = ((size_t)b * SEQ + row_lo) * EMBED + h * HDIM;
    size_t base_hi = base_lo + (size_t)8 * EMBED;
    float il_lo = 1.f / l_lo, il_hi = 1.f / l_hi;
#pragma unroll
    for (int ni = 0; ni < 16; ni++) {
        int c = ni * 8 + tig * 2;
        *(__half2*)(Ctx + base_lo + c) = __floats2half2_rn(o[ni][0]*il_lo, o[ni][1]*il_lo);
        *(__half2*)(Ctx + base_hi + c) = __floats2half2_rn(o[ni][2]*il_hi, o[ni][3]*il_hi);
    }
}

// ---------------------------------------------------------------------------
extern "C" void kernel_launch(void* const* d_in, const int* in_sizes, int n_in,
                              void* d_out, int out_size) {
    const float* x  = (const float*)d_in[0];
    const float* Wq = (const float*)d_in[1];
    const float* bq = (const float*)d_in[2];
    const float* Wk = (const float*)d_in[3];
    const float* bk = (const float*)d_in[4];
    const float* Wv = (const float*)d_in[5];
    const float* bv = (const float*)d_in[6];
    const float* Wo = (const float*)d_in[7];
    const float* bo = (const float*)d_in[8];
    float* out = (float*)d_out;

    __half *Qb, *Kb, *Vb, *Cb, *xh, *Wh;
    cudaGetSymbolAddress((void**)&Qb, g_Q);
    cudaGetSymbolAddress((void**)&Kb, g_K);
    cudaGetSymbolAddress((void**)&Vb, g_V);
    cudaGetSymbolAddress((void**)&Cb, g_C);
    cudaGetSymbolAddress((void**)&xh, g_xh);
    cudaGetSymbolAddress((void**)&Wh, g_Wh);
    __half* Woh = Wh + (size_t)3 * EMBED * EMBED;

    const int total4 = XN4 + 4 * WN4;   // 6,291,456
    f2h_all_kernel<<<total4 / 256, 256>>>(x, Wq, Wk, Wv, Wo, xh, Wh);

    cudaFuncSetAttribute(gemm_f16_kernel,
                         cudaFuncAttributeMaxDynamicSharedMemorySize, GEMM_SMEM);

    // Fused QKV: grid.z = 3 selects Wq/Wk/Wv slab of Wh, bias, output.
    dim3 gqkv(EMBED / 128, MROWS / 128, 3);   // 1536 CTAs = 5.2 waves
    gemm_f16_kernel<<<gqkv, 256, GEMM_SMEM>>>(xh, Wh, bq, bk, bv,
                                              Qb, Kb, Vb, 1);

    cudaFuncSetAttribute(attn_kernel,
                         cudaFuncAttributeMaxDynamicSharedMemorySize, ATTN_SMEM);
    attn_kernel<<<dim3(SEQ / 64, BATCH * NHEAD), 128, ATTN_SMEM>>>(Qb, Kb, Vb, Cb);

    // O-projection: z=0 -> Woh, bo, out; fp32 out.
    dim3 go(EMBED / 128, MROWS / 128, 1);     // 512 CTAs
    gemm_f16_kernel<<<go, 256, GEMM_SMEM>>>(Cb, Woh, bo, bo, bo,
                                            out, out, out, 0);
}